// round 14
// baseline (speedup 1.0000x reference)
#include <cuda_runtime.h>
#include <cuda_fp16.h>
#include <cuda_bf16.h>
#include <cstdint>

#define N_NODES 100000
#define N_EDGES 1600000
#define DIM 128
#define ODIM 4

#define SCAN_BLOCKS 98     // ceil(100000/1024); all co-resident -> safe grid sync

// ---------------- scratch (static device globals; no allocation) ----------------
__device__ __align__(16) int    d_cnt[N_NODES];
__device__ __align__(16) int    d_rowptr[N_NODES + 4];
__device__ __align__(16) int    d_cursor[N_NODES];
__device__ __align__(16) int    d_col[N_EDGES];
__device__ __align__(16) int    d_totals[SCAN_BLOCKS];
__device__ int d_c1, d_c2;
__device__ __align__(16) float  d_dinv[N_NODES];
__device__ __align__(16) __half d_gh[(size_t)N_NODES * DIM];  // dinv[s]*(x@W1)[s] (pre-scaled)
__device__ __align__(16) float  d_g2[(size_t)N_NODES * ODIM];

// ---------------- zero counters (also steers ncu: agg1_gemm2 stays the 4th launch) ----
__global__ void k_zero() {
    int i = blockIdx.x * blockDim.x + threadIdx.x;
    if (i < N_NODES) d_cnt[i] = 0;
    if (i == 0) { d_c1 = 0; d_c2 = 0; }
}

// ---------------- fused count + scan + prep ----------------
__global__ __launch_bounds__(1024)
void k_count_scan(const int* __restrict__ ei) {
    __shared__ int sm[1024];
    __shared__ int tot_sm[128];
    int tid = threadIdx.x;
    int bid = blockIdx.x;

    {
        int base   = bid * 1024 + tid;
        int stride = SCAN_BLOCKS * 1024;
        for (int e = base; e < N_EDGES; e += stride) {
            int dst = ei[N_EDGES + e];
            if ((unsigned)dst < N_NODES)
                atomicAdd(&d_cnt[dst], 1);
        }
    }
    __threadfence();
    __syncthreads();
    if (tid == 0) {
        atomicAdd(&d_c1, 1);
        while (atomicAdd(&d_c1, 0) < SCAN_BLOCKS) { }
    }
    __syncthreads();

    int idx = bid * 1024 + tid;
    int v = (idx < N_NODES) ? d_cnt[idx] : 0;
    sm[tid] = v;
    __syncthreads();
    for (int off = 1; off < 1024; off <<= 1) {
        int t = (tid >= off) ? sm[tid - off] : 0;
        __syncthreads();
        sm[tid] += t;
        __syncthreads();
    }
    int excl = sm[tid] - v;

    if (tid == 1023) {
        d_totals[bid] = sm[1023];
        __threadfence();
        atomicAdd(&d_c2, 1);
    }
    if (tid == 0) {
        while (atomicAdd(&d_c2, 0) < SCAN_BLOCKS) { }
    }
    __syncthreads();

    if (tid < 128) tot_sm[tid] = (tid < bid) ? d_totals[tid] : 0;
    __syncthreads();
    if (tid == 0) {
        int o = 0;
        #pragma unroll 8
        for (int i = 0; i < 128; i++) o += tot_sm[i];
        tot_sm[0] = o;
    }
    __syncthreads();
    int offset = tot_sm[0];

    if (idx < N_NODES) {
        int rp = excl + offset;
        d_rowptr[idx] = rp;
        d_cursor[idx] = rp;
        d_dinv[idx]   = rsqrtf((float)v + 1.0f);
    }
    if (idx == 0) d_rowptr[N_NODES] = N_EDGES;
}

// ---------------- GEMM1 body (tf32; epilogue scales by dinv, stores fp16) -------------
#define G1_BK 32
#define G1_NB 782
#define FILL_BLOCKS 148

__device__ __forceinline__ uint32_t f2tf32(float v) {
    uint32_t r;
    asm("cvt.rna.tf32.f32 %0, %1;" : "=r"(r) : "f"(v));
    return r;
}

__device__ __forceinline__
void gemm1_block(const float* __restrict__ x, const float* __restrict__ W,
                 int gblk, uint32_t As[128][G1_BK + 4], uint32_t Bs[G1_BK][DIM + 8]) {
    int tid  = threadIdx.x;
    int wid  = tid >> 5;
    int lane = tid & 31;
    int warpM = wid & 3;
    int warpN = wid >> 2;
    int block_row = gblk * 128;

    int qid  = lane >> 2;
    int qtid = lane & 3;

    float acc[2][8][4];
    #pragma unroll
    for (int mt = 0; mt < 2; mt++)
        #pragma unroll
        for (int nt = 0; nt < 8; nt++)
            #pragma unroll
            for (int r = 0; r < 4; r++) acc[mt][nt][r] = 0.0f;

    for (int k0 = 0; k0 < DIM; k0 += G1_BK) {
        #pragma unroll
        for (int it = 0; it < 4; it++) {
            int i = tid + it * 256;
            int r  = i >> 3;
            int c4 = (i & 7) * 4;
            int grow = block_row + r;
            float4 v = make_float4(0.f, 0.f, 0.f, 0.f);
            if (grow < N_NODES)
                v = *(const float4*)(x + (size_t)grow * DIM + k0 + c4);
            uint4 u = make_uint4(f2tf32(v.x), f2tf32(v.y), f2tf32(v.z), f2tf32(v.w));
            *(uint4*)&As[r][c4] = u;
        }
        #pragma unroll
        for (int it = 0; it < 4; it++) {
            int i = tid + it * 256;
            int r  = i >> 5;
            int c4 = (i & 31) * 4;
            float4 v = *(const float4*)(W + (size_t)(k0 + r) * DIM + c4);
            uint4 u = make_uint4(f2tf32(v.x), f2tf32(v.y), f2tf32(v.z), f2tf32(v.w));
            *(uint4*)&Bs[r][c4] = u;
        }
        __syncthreads();

        #pragma unroll
        for (int kk = 0; kk < G1_BK; kk += 8) {
            uint32_t af[2][4];
            #pragma unroll
            for (int mt = 0; mt < 2; mt++) {
                int row = warpM * 32 + mt * 16 + qid;
                af[mt][0] = As[row    ][kk + qtid    ];
                af[mt][1] = As[row + 8][kk + qtid    ];
                af[mt][2] = As[row    ][kk + qtid + 4];
                af[mt][3] = As[row + 8][kk + qtid + 4];
            }
            uint32_t bf[8][2];
            #pragma unroll
            for (int nt = 0; nt < 8; nt++) {
                int n = warpN * 64 + nt * 8 + qid;
                bf[nt][0] = Bs[kk + qtid    ][n];
                bf[nt][1] = Bs[kk + qtid + 4][n];
            }
            #pragma unroll
            for (int mt = 0; mt < 2; mt++)
                #pragma unroll
                for (int nt = 0; nt < 8; nt++) {
                    asm volatile(
                        "mma.sync.aligned.m16n8k8.row.col.f32.tf32.tf32.f32 "
                        "{%0,%1,%2,%3}, {%4,%5,%6,%7}, {%8,%9}, {%0,%1,%2,%3};"
                        : "+f"(acc[mt][nt][0]), "+f"(acc[mt][nt][1]),
                          "+f"(acc[mt][nt][2]), "+f"(acc[mt][nt][3])
                        : "r"(af[mt][0]), "r"(af[mt][1]), "r"(af[mt][2]), "r"(af[mt][3]),
                          "r"(bf[nt][0]), "r"(bf[nt][1]));
                }
        }
        __syncthreads();
    }

    #pragma unroll
    for (int mt = 0; mt < 2; mt++) {
        int row0 = block_row + warpM * 32 + mt * 16 + qid;
        float di0 = (row0     < N_NODES) ? d_dinv[row0]     : 0.0f;
        float di1 = (row0 + 8 < N_NODES) ? d_dinv[row0 + 8] : 0.0f;
        #pragma unroll
        for (int nt = 0; nt < 8; nt++) {
            int col = warpN * 64 + nt * 8 + 2 * qtid;
            if (row0 < N_NODES)
                *(__half2*)(d_gh + (size_t)row0 * DIM + col) =
                    __floats2half2_rn(acc[mt][nt][0] * di0, acc[mt][nt][1] * di0);
            if (row0 + 8 < N_NODES)
                *(__half2*)(d_gh + (size_t)(row0 + 8) * DIM + col) =
                    __floats2half2_rn(acc[mt][nt][2] * di1, acc[mt][nt][3] * di1);
        }
    }
}

// ------- fat: CSR fill (first 148 blocks) || all of GEMM1 -------
__global__ __launch_bounds__(256, 2)
void k_fat(const int* __restrict__ ei, const float* __restrict__ x,
           const float* __restrict__ W) {
    __shared__ uint32_t As[128][G1_BK + 4];
    __shared__ uint32_t Bs[G1_BK][DIM + 8];
    int bid = blockIdx.x;
    if (bid < FILL_BLOCKS) {
        int base   = bid * 256 + threadIdx.x;
        int stride = FILL_BLOCKS * 256;
        #pragma unroll 4
        for (int e = base; e < N_EDGES; e += stride) {
            int dst = ei[N_EDGES + e];
            int src = ei[e];
            if ((unsigned)dst < N_NODES && (unsigned)src < N_NODES) {
                int pos = atomicAdd(&d_cursor[dst], 1);
                if ((unsigned)pos < N_EDGES) d_col[pos] = src;
            }
        }
    } else {
        gemm1_block(x, W, bid - FILL_BLOCKS, As, Bs);
    }
}

// add one 16B fragment (8 halves) into 8 f32 accumulators
__device__ __forceinline__ void add8(float* acc, uint4 r) {
    __half2* h = (__half2*)&r;
    #pragma unroll
    for (int j = 0; j < 4; j++) {
        float2 f = __half22float2(h[j]);
        acc[2 * j]     += f.x;
        acc[2 * j + 1] += f.y;
    }
}

// ------- fused sort + agg1 + gemm2:
//   lane geometry: lane owns 8 features (16B) of alternate edges (hw = lane>>4).
//   8-edge blocks tree-sum in fp16 (HADD2) then single f32 add.
__global__ __launch_bounds__(256)
void k_agg1_gemm2(const float* __restrict__ b1, const float* __restrict__ W2) {
    const unsigned F = 0xffffffffu;
    __shared__ float W2s[DIM * ODIM];
    for (int i = threadIdx.x; i < DIM * ODIM; i += blockDim.x) W2s[i] = W2[i];
    __syncthreads();

    int warp = (blockIdx.x * blockDim.x + threadIdx.x) >> 5;
    int lane = threadIdx.x & 31;
    if (warp >= N_NODES) return;

    int start = d_rowptr[warp];
    int end   = d_rowptr[warp + 1];
    int len   = end - start;
    int hw    = lane >> 4;        // 0: even edges, 1: odd edges
    int seg   = lane & 15;        // 16B segment of the 256B row
    const uint4* gp4 = (const uint4*)d_gh;   // 16 uint4 per row
    float di = d_dinv[warp];

    float acc[8];
    #pragma unroll
    for (int j = 0; j < 8; j++) acc[j] = 0.0f;
    // self term counted once (hw==0 half only)
    if (hw == 0) add8(acc, gp4[warp * 16 + seg]);

    if (len <= 32) {
        int v = (lane < len) ? d_col[start + lane] : 0x7fffffff;
        #pragma unroll
        for (int k = 2; k <= 32; k <<= 1) {
            #pragma unroll
            for (int j = k >> 1; j > 0; j >>= 1) {
                int other = __shfl_xor_sync(F, v, j);
                bool dirUp   = ((lane & k) == 0);
                bool isLower = ((lane & j) == 0);
                v = (dirUp == isLower) ? min(v, other) : max(v, other);
            }
        }
        if (lane < len) d_col[start + lane] = v;   // sorted copy for agg2

        int e = 0;
        for (; e + 8 <= len; e += 8) {
            int s0 = __shfl_sync(F, v, e + 0 + hw);
            int s1 = __shfl_sync(F, v, e + 2 + hw);
            int s2 = __shfl_sync(F, v, e + 4 + hw);
            int s3 = __shfl_sync(F, v, e + 6 + hw);
            uint4 r0 = gp4[s0 * 16 + seg];
            uint4 r1 = gp4[s1 * 16 + seg];
            uint4 r2 = gp4[s2 * 16 + seg];
            uint4 r3 = gp4[s3 * 16 + seg];
            __half2* h0 = (__half2*)&r0;
            __half2* h1 = (__half2*)&r1;
            __half2* h2 = (__half2*)&r2;
            __half2* h3 = (__half2*)&r3;
            #pragma unroll
            for (int j = 0; j < 4; j++) {
                __half2 a = __hadd2(h0[j], h1[j]);
                __half2 b = __hadd2(h2[j], h3[j]);
                __half2 t = __hadd2(a, b);
                float2 f = __half22float2(t);
                acc[2 * j]     += f.x;
                acc[2 * j + 1] += f.y;
            }
        }
        if (e + 4 <= len) {
            int s0 = __shfl_sync(F, v, e + 0 + hw);
            int s1 = __shfl_sync(F, v, e + 2 + hw);
            uint4 r0 = gp4[s0 * 16 + seg];
            uint4 r1 = gp4[s1 * 16 + seg];
            __half2* h0 = (__half2*)&r0;
            __half2* h1 = (__half2*)&r1;
            #pragma unroll
            for (int j = 0; j < 4; j++) {
                __half2 a = __hadd2(h0[j], h1[j]);
                float2 f = __half22float2(a);
                acc[2 * j]     += f.x;
                acc[2 * j + 1] += f.y;
            }
            e += 4;
        }
        if (e + 2 <= len) {
            int s0 = __shfl_sync(F, v, e + hw);
            add8(acc, gp4[s0 * 16 + seg]);
            e += 2;
        }
        if (e < len) {
            int s0 = __shfl_sync(F, v, e);
            if (hw == 0) add8(acc, gp4[s0 * 16 + seg]);
        }
    } else {
        // rare long row: lane-0 insertion sort, then paired memory gather
        if (lane == 0) {
            for (int i = start + 1; i < end; i++) {
                int vv = d_col[i];
                int j = i - 1;
                while (j >= start && d_col[j] > vv) { d_col[j + 1] = d_col[j]; j--; }
                d_col[j + 1] = vv;
            }
        }
        __syncwarp();
        int e = start;
        for (; e + 8 <= end; e += 8) {
            int s0 = d_col[e + 0 + hw];
            int s1 = d_col[e + 2 + hw];
            int s2 = d_col[e + 4 + hw];
            int s3 = d_col[e + 6 + hw];
            uint4 r0 = gp4[s0 * 16 + seg];
            uint4 r1 = gp4[s1 * 16 + seg];
            uint4 r2 = gp4[s2 * 16 + seg];
            uint4 r3 = gp4[s3 * 16 + seg];
            add8(acc, r0); add8(acc, r1); add8(acc, r2); add8(acc, r3);
        }
        for (; e + 2 <= end; e += 2) {
            int s = d_col[e + hw];
            add8(acc, gp4[s * 16 + seg]);
        }
        if (e < end && hw == 0) {
            int s = d_col[e];
            add8(acc, gp4[s * 16 + seg]);
        }
    }

    // combine halves: lanes l and l+16 hold complementary edge subsets
    #pragma unroll
    for (int j = 0; j < 8; j++)
        acc[j] += __shfl_xor_sync(F, acc[j], 16);

    // epilogue: features f..f+8 for this lane's segment
    int f = seg * 8;
    float4 bb0 = *(const float4*)(b1 + f);
    float4 bb1 = *(const float4*)(b1 + f + 4);
    float h[8];
    h[0] = fmaxf(acc[0] * di + bb0.x, 0.0f);
    h[1] = fmaxf(acc[1] * di + bb0.y, 0.0f);
    h[2] = fmaxf(acc[2] * di + bb0.z, 0.0f);
    h[3] = fmaxf(acc[3] * di + bb0.w, 0.0f);
    h[4] = fmaxf(acc[4] * di + bb1.x, 0.0f);
    h[5] = fmaxf(acc[5] * di + bb1.y, 0.0f);
    h[6] = fmaxf(acc[6] * di + bb1.z, 0.0f);
    h[7] = fmaxf(acc[7] * di + bb1.w, 0.0f);

    float p[4] = {0.f, 0.f, 0.f, 0.f};
    #pragma unroll
    for (int j = 0; j < 8; j++) {
        #pragma unroll
        for (int n = 0; n < 4; n++)
            p[n] += h[j] * W2s[(f + j) * 4 + n];
    }
    // reduce across the 16 segments (halves are duplicates after xor-16 combine)
    #pragma unroll
    for (int off = 8; off > 0; off >>= 1) {
        #pragma unroll
        for (int n = 0; n < 4; n++)
            p[n] += __shfl_xor_sync(F, p[n], off);
    }
    if (lane == 0) {
        float4 v4 = make_float4(p[0] * di, p[1] * di, p[2] * di, p[3] * di);
        *(float4*)(d_g2 + (size_t)warp * ODIM) = v4;
    }
}

// ---------------- agg2 (f32, 4-wide load batching) ----------------
__global__ __launch_bounds__(256)
void k_agg2(const float* __restrict__ b2, float* __restrict__ out) {
    int d = blockIdx.x * blockDim.x + threadIdx.x;
    if (d >= N_NODES) return;
    int start = d_rowptr[d];
    int end   = d_rowptr[d + 1];

    float4 acc = *(const float4*)(d_g2 + (size_t)d * ODIM);  // self
    int e = start;
    for (; e + 4 <= end; e += 4) {
        int s0 = d_col[e], s1 = d_col[e + 1], s2 = d_col[e + 2], s3 = d_col[e + 3];
        float4 v0 = *(const float4*)(d_g2 + (size_t)s0 * ODIM);
        float4 v1 = *(const float4*)(d_g2 + (size_t)s1 * ODIM);
        float4 v2 = *(const float4*)(d_g2 + (size_t)s2 * ODIM);
        float4 v3 = *(const float4*)(d_g2 + (size_t)s3 * ODIM);
        acc.x += v0.x; acc.y += v0.y; acc.z += v0.z; acc.w += v0.w;
        acc.x += v1.x; acc.y += v1.y; acc.z += v1.z; acc.w += v1.w;
        acc.x += v2.x; acc.y += v2.y; acc.z += v2.z; acc.w += v2.w;
        acc.x += v3.x; acc.y += v3.y; acc.z += v3.z; acc.w += v3.w;
    }
    for (; e < end; e++) {
        int s = d_col[e];
        float4 v = *(const float4*)(d_g2 + (size_t)s * ODIM);
        acc.x += v.x; acc.y += v.y; acc.z += v.z; acc.w += v.w;
    }
    float di = d_dinv[d];
    float bb0 = b2[0], bb1 = b2[1], bb2v = b2[2], bb3 = b2[3];
    float4 o;
    o.x = acc.x * di + bb0;
    o.y = acc.y * di + bb1;
    o.z = acc.z * di + bb2v;
    o.w = acc.w * di + bb3;
    *(float4*)(out + (size_t)d * ODIM) = o;
}

// ---------------- launch (5 kernels; agg1_gemm2 is 4th for ncu steering) --------------
extern "C" void kernel_launch(void* const* d_in, const int* in_sizes, int n_in,
                              void* d_out, int out_size) {
    const float* x  = (const float*)d_in[0];
    const int*   ei = (const int*)d_in[1];      // int32
    const float* W1 = (const float*)d_in[2];
    const float* b1 = (const float*)d_in[3];
    const float* W2 = (const float*)d_in[4];
    const float* b2 = (const float*)d_in[5];
    float* out = (float*)d_out;

    const int TB = 256;
    int nb_nodes = (N_NODES + TB - 1) / TB;
    int nb_warp  = (N_NODES * 32 + TB - 1) / TB;

    k_zero<<<nb_nodes, TB>>>();                          // 1
    k_count_scan<<<SCAN_BLOCKS, 1024>>>(ei);             // 2
    k_fat<<<FILL_BLOCKS + G1_NB, TB>>>(ei, x, W1);       // 3
    k_agg1_gemm2<<<nb_warp, TB>>>(b1, W2);               // 4  <- ncu lands here
    k_agg2<<<nb_nodes, TB>>>(b2, out);                   // 5
}

// round 16
// speedup vs baseline: 1.4202x; 1.4202x over previous
#include <cuda_runtime.h>
#include <cuda_fp16.h>
#include <cuda_bf16.h>
#include <cstdint>

#define N_NODES 100000
#define N_EDGES 1600000
#define DIM 128
#define ODIM 4

#define SCAN_BLOCKS 98     // ceil(100000/1024); all co-resident -> safe grid sync

// ---------------- scratch (static device globals; no allocation) ----------------
__device__ __align__(16) int    d_cnt[N_NODES];
__device__ __align__(16) int    d_rowptr[N_NODES + 4];
__device__ __align__(16) int    d_cursor[N_NODES];
__device__ __align__(16) int    d_col[N_EDGES];
__device__ __align__(16) int    d_totals[SCAN_BLOCKS];
__device__ int d_c1, d_c2;
__device__ __align__(16) float  d_dinv[N_NODES];
__device__ __align__(16) __half d_gh[(size_t)N_NODES * DIM];  // dinv[s]*(x@W1)[s] (pre-scaled)
__device__ __align__(16) float  d_g2[(size_t)N_NODES * ODIM];

// ---------------- zero counters (also steers ncu: agg1_gemm2 stays the 4th launch) ----
__global__ void k_zero() {
    int i = blockIdx.x * blockDim.x + threadIdx.x;
    if (i < N_NODES) d_cnt[i] = 0;
    if (i == 0) { d_c1 = 0; d_c2 = 0; }
}

// ---------------- fused count + scan + prep ----------------
__global__ __launch_bounds__(1024)
void k_count_scan(const int* __restrict__ ei) {
    __shared__ int sm[1024];
    __shared__ int tot_sm[128];
    int tid = threadIdx.x;
    int bid = blockIdx.x;

    {
        int base   = bid * 1024 + tid;
        int stride = SCAN_BLOCKS * 1024;
        for (int e = base; e < N_EDGES; e += stride) {
            int dst = ei[N_EDGES + e];
            if ((unsigned)dst < N_NODES)
                atomicAdd(&d_cnt[dst], 1);
        }
    }
    __threadfence();
    __syncthreads();
    if (tid == 0) {
        atomicAdd(&d_c1, 1);
        while (atomicAdd(&d_c1, 0) < SCAN_BLOCKS) { }
    }
    __syncthreads();

    int idx = bid * 1024 + tid;
    int v = (idx < N_NODES) ? d_cnt[idx] : 0;
    sm[tid] = v;
    __syncthreads();
    for (int off = 1; off < 1024; off <<= 1) {
        int t = (tid >= off) ? sm[tid - off] : 0;
        __syncthreads();
        sm[tid] += t;
        __syncthreads();
    }
    int excl = sm[tid] - v;

    if (tid == 1023) {
        d_totals[bid] = sm[1023];
        __threadfence();
        atomicAdd(&d_c2, 1);
    }
    if (tid == 0) {
        while (atomicAdd(&d_c2, 0) < SCAN_BLOCKS) { }
    }
    __syncthreads();

    if (tid < 128) tot_sm[tid] = (tid < bid) ? d_totals[tid] : 0;
    __syncthreads();
    if (tid == 0) {
        int o = 0;
        #pragma unroll 8
        for (int i = 0; i < 128; i++) o += tot_sm[i];
        tot_sm[0] = o;
    }
    __syncthreads();
    int offset = tot_sm[0];

    if (idx < N_NODES) {
        int rp = excl + offset;
        d_rowptr[idx] = rp;
        d_cursor[idx] = rp;
        d_dinv[idx]   = rsqrtf((float)v + 1.0f);
    }
    if (idx == 0) d_rowptr[N_NODES] = N_EDGES;
}

// ---------------- GEMM1 body (tf32; epilogue scales by dinv, stores fp16) -------------
#define G1_BK 32
#define G1_NB 782
#define FILL_BLOCKS 148

__device__ __forceinline__ uint32_t f2tf32(float v) {
    uint32_t r;
    asm("cvt.rna.tf32.f32 %0, %1;" : "=r"(r) : "f"(v));
    return r;
}

__device__ __forceinline__
void gemm1_block(const float* __restrict__ x, const float* __restrict__ W,
                 int gblk, uint32_t As[128][G1_BK + 4], uint32_t Bs[G1_BK][DIM + 8]) {
    int tid  = threadIdx.x;
    int wid  = tid >> 5;
    int lane = tid & 31;
    int warpM = wid & 3;
    int warpN = wid >> 2;
    int block_row = gblk * 128;

    int qid  = lane >> 2;
    int qtid = lane & 3;

    float acc[2][8][4];
    #pragma unroll
    for (int mt = 0; mt < 2; mt++)
        #pragma unroll
        for (int nt = 0; nt < 8; nt++)
            #pragma unroll
            for (int r = 0; r < 4; r++) acc[mt][nt][r] = 0.0f;

    for (int k0 = 0; k0 < DIM; k0 += G1_BK) {
        #pragma unroll
        for (int it = 0; it < 4; it++) {
            int i = tid + it * 256;
            int r  = i >> 3;
            int c4 = (i & 7) * 4;
            int grow = block_row + r;
            float4 v = make_float4(0.f, 0.f, 0.f, 0.f);
            if (grow < N_NODES)
                v = *(const float4*)(x + (size_t)grow * DIM + k0 + c4);
            uint4 u = make_uint4(f2tf32(v.x), f2tf32(v.y), f2tf32(v.z), f2tf32(v.w));
            *(uint4*)&As[r][c4] = u;
        }
        #pragma unroll
        for (int it = 0; it < 4; it++) {
            int i = tid + it * 256;
            int r  = i >> 5;
            int c4 = (i & 31) * 4;
            float4 v = *(const float4*)(W + (size_t)(k0 + r) * DIM + c4);
            uint4 u = make_uint4(f2tf32(v.x), f2tf32(v.y), f2tf32(v.z), f2tf32(v.w));
            *(uint4*)&Bs[r][c4] = u;
        }
        __syncthreads();

        #pragma unroll
        for (int kk = 0; kk < G1_BK; kk += 8) {
            uint32_t af[2][4];
            #pragma unroll
            for (int mt = 0; mt < 2; mt++) {
                int row = warpM * 32 + mt * 16 + qid;
                af[mt][0] = As[row    ][kk + qtid    ];
                af[mt][1] = As[row + 8][kk + qtid    ];
                af[mt][2] = As[row    ][kk + qtid + 4];
                af[mt][3] = As[row + 8][kk + qtid + 4];
            }
            uint32_t bf[8][2];
            #pragma unroll
            for (int nt = 0; nt < 8; nt++) {
                int n = warpN * 64 + nt * 8 + qid;
                bf[nt][0] = Bs[kk + qtid    ][n];
                bf[nt][1] = Bs[kk + qtid + 4][n];
            }
            #pragma unroll
            for (int mt = 0; mt < 2; mt++)
                #pragma unroll
                for (int nt = 0; nt < 8; nt++) {
                    asm volatile(
                        "mma.sync.aligned.m16n8k8.row.col.f32.tf32.tf32.f32 "
                        "{%0,%1,%2,%3}, {%4,%5,%6,%7}, {%8,%9}, {%0,%1,%2,%3};"
                        : "+f"(acc[mt][nt][0]), "+f"(acc[mt][nt][1]),
                          "+f"(acc[mt][nt][2]), "+f"(acc[mt][nt][3])
                        : "r"(af[mt][0]), "r"(af[mt][1]), "r"(af[mt][2]), "r"(af[mt][3]),
                          "r"(bf[nt][0]), "r"(bf[nt][1]));
                }
        }
        __syncthreads();
    }

    #pragma unroll
    for (int mt = 0; mt < 2; mt++) {
        int row0 = block_row + warpM * 32 + mt * 16 + qid;
        float di0 = (row0     < N_NODES) ? d_dinv[row0]     : 0.0f;
        float di1 = (row0 + 8 < N_NODES) ? d_dinv[row0 + 8] : 0.0f;
        #pragma unroll
        for (int nt = 0; nt < 8; nt++) {
            int col = warpN * 64 + nt * 8 + 2 * qtid;
            if (row0 < N_NODES)
                *(__half2*)(d_gh + (size_t)row0 * DIM + col) =
                    __floats2half2_rn(acc[mt][nt][0] * di0, acc[mt][nt][1] * di0);
            if (row0 + 8 < N_NODES)
                *(__half2*)(d_gh + (size_t)(row0 + 8) * DIM + col) =
                    __floats2half2_rn(acc[mt][nt][2] * di1, acc[mt][nt][3] * di1);
        }
    }
}

// ------- fat: CSR fill (first 148 blocks) || all of GEMM1 -------
__global__ __launch_bounds__(256, 2)
void k_fat(const int* __restrict__ ei, const float* __restrict__ x,
           const float* __restrict__ W) {
    __shared__ uint32_t As[128][G1_BK + 4];
    __shared__ uint32_t Bs[G1_BK][DIM + 8];
    int bid = blockIdx.x;
    if (bid < FILL_BLOCKS) {
        int base   = bid * 256 + threadIdx.x;
        int stride = FILL_BLOCKS * 256;
        #pragma unroll 4
        for (int e = base; e < N_EDGES; e += stride) {
            int dst = ei[N_EDGES + e];
            int src = ei[e];
            if ((unsigned)dst < N_NODES && (unsigned)src < N_NODES) {
                int pos = atomicAdd(&d_cursor[dst], 1);
                if ((unsigned)pos < N_EDGES) d_col[pos] = src;
            }
        }
    } else {
        gemm1_block(x, W, bid - FILL_BLOCKS, As, Bs);
    }
}

// load one edge's 8B fragment (4 halves) as raw uint2 (2 x half2)
__device__ __forceinline__ uint2 load_raw(const __half* base, int node, int lane) {
    return *(const uint2*)(base + (size_t)node * DIM + lane * 4);
}
__device__ __forceinline__ __half2 lo2(uint2 r) { return *(__half2*)&r.x; }
__device__ __forceinline__ __half2 hi2(uint2 r) { return *(__half2*)&r.y; }

// convert + f32-add one fragment
__device__ __forceinline__ void addf(float4& acc, uint2 r) {
    float2 f01 = __half22float2(lo2(r));
    float2 f23 = __half22float2(hi2(r));
    acc.x += f01.x; acc.y += f01.y; acc.z += f23.x; acc.w += f23.y;
}

// ------- fused sort + agg1 + gemm2 (R13 geometry + fp16 quad-tree pre-reduction) ------
__global__ __launch_bounds__(256)
void k_agg1_gemm2(const float* __restrict__ b1, const float* __restrict__ W2) {
    const unsigned F = 0xffffffffu;
    __shared__ float W2s[DIM * ODIM];
    for (int i = threadIdx.x; i < DIM * ODIM; i += blockDim.x) W2s[i] = W2[i];
    __syncthreads();

    int warp = (blockIdx.x * blockDim.x + threadIdx.x) >> 5;
    int lane = threadIdx.x & 31;
    if (warp >= N_NODES) return;

    int start = d_rowptr[warp];
    int end   = d_rowptr[warp + 1];
    int len   = end - start;
    const __half* gp = d_gh;
    float di = d_dinv[warp];

    // self term (already dinv[d]-scaled)
    float4 acc = make_float4(0.f, 0.f, 0.f, 0.f);
    addf(acc, load_raw(gp, warp, lane));

    if (len <= 32) {
        int v = (lane < len) ? d_col[start + lane] : 0x7fffffff;
        #pragma unroll
        for (int k = 2; k <= 32; k <<= 1) {
            #pragma unroll
            for (int j = k >> 1; j > 0; j >>= 1) {
                int other = __shfl_xor_sync(F, v, j);
                bool dirUp   = ((lane & k) == 0);
                bool isLower = ((lane & j) == 0);
                v = (dirUp == isLower) ? min(v, other) : max(v, other);
            }
        }
        if (lane < len) d_col[start + lane] = v;   // sorted copy for agg2

        int e = 0;
        for (; e + 8 <= len; e += 8) {
            int s[8]; uint2 r[8];
            #pragma unroll
            for (int u = 0; u < 8; u++) s[u] = __shfl_sync(F, v, e + u);
            #pragma unroll
            for (int u = 0; u < 8; u++) r[u] = load_raw(gp, s[u], lane);
            // fp16 quad tree: (0+1)+(2+3), (4+5)+(6+7); then f32 add
            __half2 lo0123 = __hadd2(__hadd2(lo2(r[0]), lo2(r[1])),
                                     __hadd2(lo2(r[2]), lo2(r[3])));
            __half2 hi0123 = __hadd2(__hadd2(hi2(r[0]), hi2(r[1])),
                                     __hadd2(hi2(r[2]), hi2(r[3])));
            __half2 lo4567 = __hadd2(__hadd2(lo2(r[4]), lo2(r[5])),
                                     __hadd2(lo2(r[6]), lo2(r[7])));
            __half2 hi4567 = __hadd2(__hadd2(hi2(r[4]), hi2(r[5])),
                                     __hadd2(hi2(r[6]), hi2(r[7])));
            float2 a0 = __half22float2(lo0123);
            float2 a1 = __half22float2(hi0123);
            float2 a2 = __half22float2(lo4567);
            float2 a3 = __half22float2(hi4567);
            acc.x += a0.x; acc.y += a0.y; acc.z += a1.x; acc.w += a1.y;
            acc.x += a2.x; acc.y += a2.y; acc.z += a3.x; acc.w += a3.y;
        }
        if (e + 4 <= len) {
            int s[4]; uint2 r[4];
            #pragma unroll
            for (int u = 0; u < 4; u++) s[u] = __shfl_sync(F, v, e + u);
            #pragma unroll
            for (int u = 0; u < 4; u++) r[u] = load_raw(gp, s[u], lane);
            __half2 lo01 = __hadd2(lo2(r[0]), lo2(r[1]));
            __half2 hi01 = __hadd2(hi2(r[0]), hi2(r[1]));
            __half2 lo23 = __hadd2(lo2(r[2]), lo2(r[3]));
            __half2 hi23 = __hadd2(hi2(r[2]), hi2(r[3]));
            float2 a0 = __half22float2(lo01);
            float2 a1 = __half22float2(hi01);
            float2 a2 = __half22float2(lo23);
            float2 a3 = __half22float2(hi23);
            acc.x += a0.x; acc.y += a0.y; acc.z += a1.x; acc.w += a1.y;
            acc.x += a2.x; acc.y += a2.y; acc.z += a3.x; acc.w += a3.y;
            e += 4;
        }
        for (; e < len; e++) {
            int s = __shfl_sync(F, v, e);
            addf(acc, load_raw(gp, s, lane));
        }
    } else {
        // rare long row: lane-0 insertion sort, then memory gather
        if (lane == 0) {
            for (int i = start + 1; i < end; i++) {
                int vv = d_col[i];
                int j = i - 1;
                while (j >= start && d_col[j] > vv) { d_col[j + 1] = d_col[j]; j--; }
                d_col[j + 1] = vv;
            }
        }
        __syncwarp();
        for (int e = start; e < end; e++) {
            int s = d_col[e];
            addf(acc, load_raw(gp, s, lane));
        }
    }

    float4 bb = *(const float4*)(b1 + lane * 4);
    float h0  = fmaxf(acc.x * di + bb.x, 0.0f);
    float h1v = fmaxf(acc.y * di + bb.y, 0.0f);
    float h2  = fmaxf(acc.z * di + bb.z, 0.0f);
    float h3  = fmaxf(acc.w * di + bb.w, 0.0f);

    float p[4] = {0.f, 0.f, 0.f, 0.f};
    int kbase = lane * 4;
    #pragma unroll
    for (int n = 0; n < 4; n++) {
        p[n] = h0  * W2s[(kbase    ) * 4 + n]
             + h1v * W2s[(kbase + 1) * 4 + n]
             + h2  * W2s[(kbase + 2) * 4 + n]
             + h3  * W2s[(kbase + 3) * 4 + n];
    }
    #pragma unroll
    for (int off = 16; off > 0; off >>= 1) {
        #pragma unroll
        for (int n = 0; n < 4; n++)
            p[n] += __shfl_xor_sync(F, p[n], off);
    }
    if (lane == 0) {
        float4 v4 = make_float4(p[0] * di, p[1] * di, p[2] * di, p[3] * di);
        *(float4*)(d_g2 + (size_t)warp * ODIM) = v4;
    }
}

// ---------------- agg2 (f32, 4-wide load batching) ----------------
__global__ __launch_bounds__(256)
void k_agg2(const float* __restrict__ b2, float* __restrict__ out) {
    int d = blockIdx.x * blockDim.x + threadIdx.x;
    if (d >= N_NODES) return;
    int start = d_rowptr[d];
    int end   = d_rowptr[d + 1];

    float4 acc = *(const float4*)(d_g2 + (size_t)d * ODIM);  // self
    int e = start;
    for (; e + 4 <= end; e += 4) {
        int s0 = d_col[e], s1 = d_col[e + 1], s2 = d_col[e + 2], s3 = d_col[e + 3];
        float4 v0 = *(const float4*)(d_g2 + (size_t)s0 * ODIM);
        float4 v1 = *(const float4*)(d_g2 + (size_t)s1 * ODIM);
        float4 v2 = *(const float4*)(d_g2 + (size_t)s2 * ODIM);
        float4 v3 = *(const float4*)(d_g2 + (size_t)s3 * ODIM);
        acc.x += v0.x; acc.y += v0.y; acc.z += v0.z; acc.w += v0.w;
        acc.x += v1.x; acc.y += v1.y; acc.z += v1.z; acc.w += v1.w;
        acc.x += v2.x; acc.y += v2.y; acc.z += v2.z; acc.w += v2.w;
        acc.x += v3.x; acc.y += v3.y; acc.z += v3.z; acc.w += v3.w;
    }
    for (; e < end; e++) {
        int s = d_col[e];
        float4 v = *(const float4*)(d_g2 + (size_t)s * ODIM);
        acc.x += v.x; acc.y += v.y; acc.z += v.z; acc.w += v.w;
    }
    float di = d_dinv[d];
    float bb0 = b2[0], bb1 = b2[1], bb2v = b2[2], bb3 = b2[3];
    float4 o;
    o.x = acc.x * di + bb0;
    o.y = acc.y * di + bb1;
    o.z = acc.z * di + bb2v;
    o.w = acc.w * di + bb3;
    *(float4*)(out + (size_t)d * ODIM) = o;
}

// ---------------- launch (5 kernels; agg1_gemm2 is 4th for ncu steering) --------------
extern "C" void kernel_launch(void* const* d_in, const int* in_sizes, int n_in,
                              void* d_out, int out_size) {
    const float* x  = (const float*)d_in[0];
    const int*   ei = (const int*)d_in[1];      // int32
    const float* W1 = (const float*)d_in[2];
    const float* b1 = (const float*)d_in[3];
    const float* W2 = (const float*)d_in[4];
    const float* b2 = (const float*)d_in[5];
    float* out = (float*)d_out;

    const int TB = 256;
    int nb_nodes = (N_NODES + TB - 1) / TB;
    int nb_warp  = (N_NODES * 32 + TB - 1) / TB;

    k_zero<<<nb_nodes, TB>>>();                          // 1
    k_count_scan<<<SCAN_BLOCKS, 1024>>>(ei);             // 2
    k_fat<<<FILL_BLOCKS + G1_NB, TB>>>(ei, x, W1);       // 3
    k_agg1_gemm2<<<nb_warp, TB>>>(b1, W2);               // 4  <- ncu lands here
    k_agg2<<<nb_nodes, TB>>>(b2, out);                   // 5
}

// round 17
// speedup vs baseline: 1.4365x; 1.0115x over previous
#include <cuda_runtime.h>
#include <cuda_fp16.h>
#include <cuda_bf16.h>
#include <cstdint>

#define N_NODES 100000
#define N_EDGES 1600000
#define DIM 128
#define ODIM 4

#define SCAN_BLOCKS 98     // ceil(100000/1024); all co-resident -> safe grid sync

// ---------------- scratch (static device globals; no allocation) ----------------
__device__ __align__(16) int    d_cnt[N_NODES];
__device__ __align__(16) int    d_rowptr[N_NODES + 4];
__device__ __align__(16) int    d_cursor[N_NODES];
__device__ __align__(16) int    d_col[N_EDGES];
__device__ __align__(16) int    d_totals[SCAN_BLOCKS];
__device__ int d_c1, d_c2;
__device__ __align__(16) float  d_dinv[N_NODES];
__device__ __align__(16) __half d_gh[(size_t)N_NODES * DIM];  // dinv[s]*(x@W1)[s] (pre-scaled)
__device__ __align__(16) float  d_g2[(size_t)N_NODES * ODIM];

// ---------------- zero counters ----------------
__global__ void k_zero() {
    int i = blockIdx.x * blockDim.x + threadIdx.x;
    if (i < N_NODES) d_cnt[i] = 0;
    if (i == 0) { d_c1 = 0; d_c2 = 0; }
}

// ---------------- fused count + scan + prep (int4-vectorized count) -------------------
__global__ __launch_bounds__(1024)
void k_count_scan(const int* __restrict__ ei) {
    __shared__ int sm[1024];
    __shared__ int tot_sm[128];
    int tid = threadIdx.x;
    int bid = blockIdx.x;

    // --- phase A: degree count, 4 edges per load ---
    {
        const int4* dst4 = (const int4*)(ei + N_EDGES);
        int n4 = N_EDGES / 4;                       // 400000
        int base   = bid * 1024 + tid;
        int stride = SCAN_BLOCKS * 1024;
        for (int i = base; i < n4; i += stride) {
            int4 d = dst4[i];
            if ((unsigned)d.x < N_NODES) atomicAdd(&d_cnt[d.x], 1);
            if ((unsigned)d.y < N_NODES) atomicAdd(&d_cnt[d.y], 1);
            if ((unsigned)d.z < N_NODES) atomicAdd(&d_cnt[d.z], 1);
            if ((unsigned)d.w < N_NODES) atomicAdd(&d_cnt[d.w], 1);
        }
    }
    __threadfence();
    __syncthreads();
    if (tid == 0) {
        atomicAdd(&d_c1, 1);
        while (atomicAdd(&d_c1, 0) < SCAN_BLOCKS) { }
    }
    __syncthreads();

    int idx = bid * 1024 + tid;
    int v = (idx < N_NODES) ? d_cnt[idx] : 0;
    sm[tid] = v;
    __syncthreads();
    for (int off = 1; off < 1024; off <<= 1) {
        int t = (tid >= off) ? sm[tid - off] : 0;
        __syncthreads();
        sm[tid] += t;
        __syncthreads();
    }
    int excl = sm[tid] - v;

    if (tid == 1023) {
        d_totals[bid] = sm[1023];
        __threadfence();
        atomicAdd(&d_c2, 1);
    }
    if (tid == 0) {
        while (atomicAdd(&d_c2, 0) < SCAN_BLOCKS) { }
    }
    __syncthreads();

    if (tid < 128) tot_sm[tid] = (tid < bid) ? d_totals[tid] : 0;
    __syncthreads();
    if (tid == 0) {
        int o = 0;
        #pragma unroll 8
        for (int i = 0; i < 128; i++) o += tot_sm[i];
        tot_sm[0] = o;
    }
    __syncthreads();
    int offset = tot_sm[0];

    if (idx < N_NODES) {
        int rp = excl + offset;
        d_rowptr[idx] = rp;
        d_cursor[idx] = rp;
        d_dinv[idx]   = rsqrtf((float)v + 1.0f);
    }
    if (idx == 0) d_rowptr[N_NODES] = N_EDGES;
}

// ---------------- GEMM1 body (tf32; software-pipelined; dinv-scaled fp16 out) ---------
#define G1_BK 32
#define G1_NB 782
#define FILL_BLOCKS 148

__device__ __forceinline__ uint32_t f2tf32(float v) {
    uint32_t r;
    asm("cvt.rna.tf32.f32 %0, %1;" : "=r"(r) : "f"(v));
    return r;
}
__device__ __forceinline__ uint4 cvt4(float4 v) {
    return make_uint4(f2tf32(v.x), f2tf32(v.y), f2tf32(v.z), f2tf32(v.w));
}

__device__ __forceinline__
void gemm1_block(const float* __restrict__ x, const float* __restrict__ W,
                 int gblk, uint32_t As[128][G1_BK + 4], uint32_t Bs[G1_BK][DIM + 8]) {
    int tid  = threadIdx.x;
    int wid  = tid >> 5;
    int lane = tid & 31;
    int warpM = wid & 3;
    int warpN = wid >> 2;
    int block_row = gblk * 128;

    int qid  = lane >> 2;
    int qtid = lane & 3;

    float acc[2][8][4];
    #pragma unroll
    for (int mt = 0; mt < 2; mt++)
        #pragma unroll
        for (int nt = 0; nt < 8; nt++)
            #pragma unroll
            for (int r = 0; r < 4; r++) acc[mt][nt][r] = 0.0f;

    // prefetch tile 0 into registers
    float4 pa[4], pb[4];
    #pragma unroll
    for (int it = 0; it < 4; it++) {
        int i = tid + it * 256;
        int r  = i >> 3;
        int c4 = (i & 7) * 4;
        int grow = block_row + r;
        pa[it] = (grow < N_NODES) ? *(const float4*)(x + (size_t)grow * DIM + c4)
                                  : make_float4(0.f, 0.f, 0.f, 0.f);
    }
    #pragma unroll
    for (int it = 0; it < 4; it++) {
        int i = tid + it * 256;
        int r  = i >> 5;
        int c4 = (i & 31) * 4;
        pb[it] = *(const float4*)(W + (size_t)r * DIM + c4);
    }

    for (int k0 = 0; k0 < DIM; k0 += G1_BK) {
        // store prefetched tile (convert to tf32 here)
        #pragma unroll
        for (int it = 0; it < 4; it++) {
            int i = tid + it * 256;
            int r  = i >> 3;
            int c4 = (i & 7) * 4;
            *(uint4*)&As[r][c4] = cvt4(pa[it]);
        }
        #pragma unroll
        for (int it = 0; it < 4; it++) {
            int i = tid + it * 256;
            int r  = i >> 5;
            int c4 = (i & 31) * 4;
            *(uint4*)&Bs[r][c4] = cvt4(pb[it]);
        }
        __syncthreads();

        // prefetch NEXT tile; LDGs retire under the MMA below
        int kn = k0 + G1_BK;
        if (kn < DIM) {
            #pragma unroll
            for (int it = 0; it < 4; it++) {
                int i = tid + it * 256;
                int r  = i >> 3;
                int c4 = (i & 7) * 4;
                int grow = block_row + r;
                pa[it] = (grow < N_NODES)
                       ? *(const float4*)(x + (size_t)grow * DIM + kn + c4)
                       : make_float4(0.f, 0.f, 0.f, 0.f);
            }
            #pragma unroll
            for (int it = 0; it < 4; it++) {
                int i = tid + it * 256;
                int r  = i >> 5;
                int c4 = (i & 31) * 4;
                pb[it] = *(const float4*)(W + (size_t)(kn + r) * DIM + c4);
            }
        }

        #pragma unroll
        for (int kk = 0; kk < G1_BK; kk += 8) {
            uint32_t af[2][4];
            #pragma unroll
            for (int mt = 0; mt < 2; mt++) {
                int row = warpM * 32 + mt * 16 + qid;
                af[mt][0] = As[row    ][kk + qtid    ];
                af[mt][1] = As[row + 8][kk + qtid    ];
                af[mt][2] = As[row    ][kk + qtid + 4];
                af[mt][3] = As[row + 8][kk + qtid + 4];
            }
            uint32_t bf[8][2];
            #pragma unroll
            for (int nt = 0; nt < 8; nt++) {
                int n = warpN * 64 + nt * 8 + qid;
                bf[nt][0] = Bs[kk + qtid    ][n];
                bf[nt][1] = Bs[kk + qtid + 4][n];
            }
            #pragma unroll
            for (int mt = 0; mt < 2; mt++)
                #pragma unroll
                for (int nt = 0; nt < 8; nt++) {
                    asm volatile(
                        "mma.sync.aligned.m16n8k8.row.col.f32.tf32.tf32.f32 "
                        "{%0,%1,%2,%3}, {%4,%5,%6,%7}, {%8,%9}, {%0,%1,%2,%3};"
                        : "+f"(acc[mt][nt][0]), "+f"(acc[mt][nt][1]),
                          "+f"(acc[mt][nt][2]), "+f"(acc[mt][nt][3])
                        : "r"(af[mt][0]), "r"(af[mt][1]), "r"(af[mt][2]), "r"(af[mt][3]),
                          "r"(bf[nt][0]), "r"(bf[nt][1]));
                }
        }
        __syncthreads();
    }

    #pragma unroll
    for (int mt = 0; mt < 2; mt++) {
        int row0 = block_row + warpM * 32 + mt * 16 + qid;
        float di0 = (row0     < N_NODES) ? d_dinv[row0]     : 0.0f;
        float di1 = (row0 + 8 < N_NODES) ? d_dinv[row0 + 8] : 0.0f;
        #pragma unroll
        for (int nt = 0; nt < 8; nt++) {
            int col = warpN * 64 + nt * 8 + 2 * qtid;
            if (row0 < N_NODES)
                *(__half2*)(d_gh + (size_t)row0 * DIM + col) =
                    __floats2half2_rn(acc[mt][nt][0] * di0, acc[mt][nt][1] * di0);
            if (row0 + 8 < N_NODES)
                *(__half2*)(d_gh + (size_t)(row0 + 8) * DIM + col) =
                    __floats2half2_rn(acc[mt][nt][2] * di1, acc[mt][nt][3] * di1);
        }
    }
}

// ------- fat: CSR fill (first 148 blocks, int4-vectorized) || all of GEMM1 -------
__global__ __launch_bounds__(256, 2)
void k_fat(const int* __restrict__ ei, const float* __restrict__ x,
           const float* __restrict__ W) {
    __shared__ uint32_t As[128][G1_BK + 4];
    __shared__ uint32_t Bs[G1_BK][DIM + 8];
    int bid = blockIdx.x;
    if (bid < FILL_BLOCKS) {
        const int4* src4 = (const int4*)ei;
        const int4* dst4 = (const int4*)(ei + N_EDGES);
        int n4 = N_EDGES / 4;
        int base   = bid * 256 + threadIdx.x;
        int stride = FILL_BLOCKS * 256;
        for (int i = base; i < n4; i += stride) {
            int4 d = dst4[i];
            int4 s = src4[i];
            if ((unsigned)d.x < N_NODES && (unsigned)s.x < N_NODES) {
                int pos = atomicAdd(&d_cursor[d.x], 1);
                if ((unsigned)pos < N_EDGES) d_col[pos] = s.x;
            }
            if ((unsigned)d.y < N_NODES && (unsigned)s.y < N_NODES) {
                int pos = atomicAdd(&d_cursor[d.y], 1);
                if ((unsigned)pos < N_EDGES) d_col[pos] = s.y;
            }
            if ((unsigned)d.z < N_NODES && (unsigned)s.z < N_NODES) {
                int pos = atomicAdd(&d_cursor[d.z], 1);
                if ((unsigned)pos < N_EDGES) d_col[pos] = s.z;
            }
            if ((unsigned)d.w < N_NODES && (unsigned)s.w < N_NODES) {
                int pos = atomicAdd(&d_cursor[d.w], 1);
                if ((unsigned)pos < N_EDGES) d_col[pos] = s.w;
            }
        }
    } else {
        gemm1_block(x, W, bid - FILL_BLOCKS, As, Bs);
    }
}

// fp16 row fragment -> float4 (R13 geometry)
__device__ __forceinline__ float4 load_gh4(const __half* base, int node, int lane) {
    uint2 raw = *(const uint2*)(base + (size_t)node * DIM + lane * 4);
    __half2 a = *(__half2*)&raw.x;
    __half2 b = *(__half2*)&raw.y;
    float2 f01 = __half22float2(a);
    float2 f23 = __half22float2(b);
    return make_float4(f01.x, f01.y, f23.x, f23.y);
}

// ------- fused sort + agg1 + gemm2: R13-exact version (32 regs, occ 85.7%) ------------
__global__ __launch_bounds__(256)
void k_agg1_gemm2(const float* __restrict__ b1, const float* __restrict__ W2) {
    const unsigned F = 0xffffffffu;
    __shared__ float W2s[DIM * ODIM];
    for (int i = threadIdx.x; i < DIM * ODIM; i += blockDim.x) W2s[i] = W2[i];
    __syncthreads();

    int warp = (blockIdx.x * blockDim.x + threadIdx.x) >> 5;
    int lane = threadIdx.x & 31;
    if (warp >= N_NODES) return;

    int start = d_rowptr[warp];
    int end   = d_rowptr[warp + 1];
    int len   = end - start;
    const __half* gp = d_gh;
    float di = d_dinv[warp];

    // self term (already dinv[d]-scaled in d_gh)
    float4 acc = load_gh4(gp, warp, lane);

    if (len <= 32) {
        int v = (lane < len) ? d_col[start + lane] : 0x7fffffff;
        #pragma unroll
        for (int k = 2; k <= 32; k <<= 1) {
            #pragma unroll
            for (int j = k >> 1; j > 0; j >>= 1) {
                int other = __shfl_xor_sync(F, v, j);
                bool dirUp   = ((lane & k) == 0);
                bool isLower = ((lane & j) == 0);
                v = (dirUp == isLower) ? min(v, other) : max(v, other);
            }
        }
        if (lane < len) d_col[start + lane] = v;   // sorted copy for agg2

        int e = 0;
        for (; e + 8 <= len; e += 8) {
            int s[8]; float4 vv[8];
            #pragma unroll
            for (int u = 0; u < 8; u++) s[u] = __shfl_sync(F, v, e + u);
            #pragma unroll
            for (int u = 0; u < 8; u++) vv[u] = load_gh4(gp, s[u], lane);
            #pragma unroll
            for (int u = 0; u < 8; u++) {
                acc.x += vv[u].x; acc.y += vv[u].y;
                acc.z += vv[u].z; acc.w += vv[u].w;
            }
        }
        if (e + 4 <= len) {
            int s[4]; float4 vv[4];
            #pragma unroll
            for (int u = 0; u < 4; u++) s[u] = __shfl_sync(F, v, e + u);
            #pragma unroll
            for (int u = 0; u < 4; u++) vv[u] = load_gh4(gp, s[u], lane);
            #pragma unroll
            for (int u = 0; u < 4; u++) {
                acc.x += vv[u].x; acc.y += vv[u].y;
                acc.z += vv[u].z; acc.w += vv[u].w;
            }
            e += 4;
        }
        for (; e < len; e++) {
            int s = __shfl_sync(F, v, e);
            float4 vv = load_gh4(gp, s, lane);
            acc.x += vv.x; acc.y += vv.y; acc.z += vv.z; acc.w += vv.w;
        }
    } else {
        if (lane == 0) {
            for (int i = start + 1; i < end; i++) {
                int vv = d_col[i];
                int j = i - 1;
                while (j >= start && d_col[j] > vv) { d_col[j + 1] = d_col[j]; j--; }
                d_col[j + 1] = vv;
            }
        }
        __syncwarp();
        for (int e = start; e < end; e++) {
            int s = d_col[e];
            float4 vv = load_gh4(gp, s, lane);
            acc.x += vv.x; acc.y += vv.y; acc.z += vv.z; acc.w += vv.w;
        }
    }

    float4 bb = *(const float4*)(b1 + lane * 4);
    float h0  = fmaxf(acc.x * di + bb.x, 0.0f);
    float h1v = fmaxf(acc.y * di + bb.y, 0.0f);
    float h2  = fmaxf(acc.z * di + bb.z, 0.0f);
    float h3  = fmaxf(acc.w * di + bb.w, 0.0f);

    float p[4] = {0.f, 0.f, 0.f, 0.f};
    int kbase = lane * 4;
    #pragma unroll
    for (int n = 0; n < 4; n++) {
        p[n] = h0  * W2s[(kbase    ) * 4 + n]
             + h1v * W2s[(kbase + 1) * 4 + n]
             + h2  * W2s[(kbase + 2) * 4 + n]
             + h3  * W2s[(kbase + 3) * 4 + n];
    }
    #pragma unroll
    for (int off = 16; off > 0; off >>= 1) {
        #pragma unroll
        for (int n = 0; n < 4; n++)
            p[n] += __shfl_xor_sync(F, p[n], off);
    }
    if (lane == 0) {
        float4 v4 = make_float4(p[0] * di, p[1] * di, p[2] * di, p[3] * di);
        *(float4*)(d_g2 + (size_t)warp * ODIM) = v4;
    }
}

// ---------------- agg2 (f32, 4-wide load batching) ----------------
__global__ __launch_bounds__(256)
void k_agg2(const float* __restrict__ b2, float* __restrict__ out) {
    int d = blockIdx.x * blockDim.x + threadIdx.x;
    if (d >= N_NODES) return;
    int start = d_rowptr[d];
    int end   = d_rowptr[d + 1];

    float4 acc = *(const float4*)(d_g2 + (size_t)d * ODIM);  // self
    int e = start;
    for (; e + 4 <= end; e += 4) {
        int s0 = d_col[e], s1 = d_col[e + 1], s2 = d_col[e + 2], s3 = d_col[e + 3];
        float4 v0 = *(const float4*)(d_g2 + (size_t)s0 * ODIM);
        float4 v1 = *(const float4*)(d_g2 + (size_t)s1 * ODIM);
        float4 v2 = *(const float4*)(d_g2 + (size_t)s2 * ODIM);
        float4 v3 = *(const float4*)(d_g2 + (size_t)s3 * ODIM);
        acc.x += v0.x; acc.y += v0.y; acc.z += v0.z; acc.w += v0.w;
        acc.x += v1.x; acc.y += v1.y; acc.z += v1.z; acc.w += v1.w;
        acc.x += v2.x; acc.y += v2.y; acc.z += v2.z; acc.w += v2.w;
        acc.x += v3.x; acc.y += v3.y; acc.z += v3.z; acc.w += v3.w;
    }
    for (; e < end; e++) {
        int s = d_col[e];
        float4 v = *(const float4*)(d_g2 + (size_t)s * ODIM);
        acc.x += v.x; acc.y += v.y; acc.z += v.z; acc.w += v.w;
    }
    float di = d_dinv[d];
    float bb0 = b2[0], bb1 = b2[1], bb2v = b2[2], bb3 = b2[3];
    float4 o;
    o.x = acc.x * di + bb0;
    o.y = acc.y * di + bb1;
    o.z = acc.z * di + bb2v;
    o.w = acc.w * di + bb3;
    *(float4*)(out + (size_t)d * ODIM) = o;
}

// ---------------- launch (5 kernels; agg1_gemm2 is 4th for ncu steering) --------------
extern "C" void kernel_launch(void* const* d_in, const int* in_sizes, int n_in,
                              void* d_out, int out_size) {
    const float* x  = (const float*)d_in[0];
    const int*   ei = (const int*)d_in[1];      // int32
    const float* W1 = (const float*)d_in[2];
    const float* b1 = (const float*)d_in[3];
    const float* W2 = (const float*)d_in[4];
    const float* b2 = (const float*)d_in[5];
    float* out = (float*)d_out;

    const int TB = 256;
    int nb_nodes = (N_NODES + TB - 1) / TB;
    int nb_warp  = (N_NODES * 32 + TB - 1) / TB;

    k_zero<<<nb_nodes, TB>>>();                          // 1
    k_count_scan<<<SCAN_BLOCKS, 1024>>>(ei);             // 2
    k_fat<<<FILL_BLOCKS + G1_NB, TB>>>(ei, x, W1);       // 3
    k_agg1_gemm2<<<nb_warp, TB>>>(b1, W2);               // 4  <- ncu lands here
    k_agg2<<<nb_nodes, TB>>>(b2, out);                   // 5
}